// round 13
// baseline (speedup 1.0000x reference)
#include <cuda_runtime.h>
#include <cuda_fp16.h>
#include <cstdint>

#define D_DIM   512
#define V_DIM   1024
#define KSTAGES 4
#define N_FIX   65536

#define BM      128
#define BN      128
#define KC      64
#define NCHUNK  (D_DIM / KC)   // 8
#define NVPASS  (V_DIM / BN)   // 8
#define NCH_ALL (NVPASS * NCHUNK)  // 64 flattened chunks

#define SCALE_B    32.0f       // exact power of 2 (codebook hi split)
#define DESCALE2   0.0625f     // 2 / SCALE_B
#define TAU        4e-3f       // rescue margin (~13 sigma of hi-only dot error)

// ---- shared memory layout (fast kernel, bytes) ----
#define SA      0                // [3 buf][128*64 halves] = 49152
#define SB      49152            // [3 buf][128*64 halves] = 49152
#define S_C2    98304            // 1024 floats = 4096
#define S_CV1   102400           // 256 floats
#define S_CI1   103424           // 256 ints
#define S_CV2   104448           // 256 floats
#define S_BV1   105472           // 128 floats
#define S_BI1   105984           // 128 ints
#define S_BV2   106496           // 128 floats
#define SMEM_FAST 107008

#define RROWS   16               // rescue rows batched per block

// ---- static device scratch (no runtime allocation) ----
__device__ float  g_c2[KSTAGES * V_DIM];
__device__ __half g_cb_hi[KSTAGES * V_DIM * D_DIM];
__device__ __half g_r_hi [(size_t)N_FIX * D_DIM];
__device__ int    g_cnt;
__device__ int    g_list[N_FIX];

// ============================ asm helpers ============================
__device__ __forceinline__ uint32_t smem_u32(const void* p) {
    uint32_t a;
    asm("{ .reg .u64 t; cvta.to.shared.u64 t, %1; cvt.u32.u64 %0, t; }" : "=r"(a) : "l"(p));
    return a;
}
__device__ __forceinline__ uint32_t swz(uint32_t off) { return off ^ ((off >> 3) & 0x70); }

#define CP_ASYNC16(s, g) asm volatile("cp.async.cg.shared.global [%0], [%1], 16;" :: "r"(s), "l"(g))
#define CP_COMMIT()      asm volatile("cp.async.commit_group;" ::: "memory")
#define CP_WAIT1()       asm volatile("cp.async.wait_group 1;" ::: "memory")
#define CP_WAIT0()       asm volatile("cp.async.wait_group 0;" ::: "memory")

#define LDSM4(d, a) \
    asm volatile("ldmatrix.sync.aligned.m8n8.x4.shared.b16 {%0,%1,%2,%3}, [%4];" \
        : "=r"((d)[0]), "=r"((d)[1]), "=r"((d)[2]), "=r"((d)[3]) : "r"(a))

#define MMA16816(c, a, b0, b1) \
    asm volatile("mma.sync.aligned.m16n8k16.row.col.f32.f16.f16.f32 " \
        "{%0,%1,%2,%3},{%4,%5,%6,%7},{%8,%9},{%0,%1,%2,%3};" \
        : "+f"((c)[0]), "+f"((c)[1]), "+f"((c)[2]), "+f"((c)[3]) \
        : "r"((a)[0]), "r"((a)[1]), "r"((a)[2]), "r"((a)[3]), "r"(b0), "r"(b1))

__device__ __forceinline__ void kahan_add(float& s, float& c, float y) {
    float t1 = __fsub_rn(y, c);
    float t2 = __fadd_rn(s, t1);
    c = __fsub_rn(__fsub_rn(t2, s), t1);
    s = t2;
}

// ============================ small kernels ============================
__global__ void rvq_c2_kernel(const float* __restrict__ cb) {
    int w = (blockIdx.x * blockDim.x + threadIdx.x) >> 5;
    int lane = threadIdx.x & 31;
    if (w >= KSTAGES * V_DIM) return;
    const float* v = cb + (size_t)w * D_DIM;
    double s = 0.0;
    for (int i = lane; i < D_DIM; i += 32) {
        float t = v[i];
        s += (double)__fmul_rn(t, t);
    }
    #pragma unroll
    for (int o = 16; o > 0; o >>= 1) s += __shfl_xor_sync(0xffffffffu, s, o);
    if (lane == 0) g_c2[w] = (float)s;
}

// hi-split: dst = fl16(scale * src); scale is an exact power of 2
__global__ void rvq_split_hi(const float* __restrict__ src, __half* __restrict__ hi,
                             float scale, size_t n8) {
    size_t i = (size_t)blockIdx.x * blockDim.x + threadIdx.x;
    if (i >= n8) return;
    const float4* p = (const float4*)(src + i * 8);
    float4 a = p[0], b = p[1];
    float v[8] = {a.x, a.y, a.z, a.w, b.x, b.y, b.z, b.w};
    uint4 hp;
    uint32_t hw[8];
    #pragma unroll
    for (int j = 0; j < 8; j++)
        hw[j] = (uint32_t)__half_as_ushort(__float2half_rn(__fmul_rn(v[j], scale)));
    hp.x = hw[0] | (hw[1] << 16);
    hp.y = hw[2] | (hw[3] << 16);
    hp.z = hw[4] | (hw[5] << 16);
    hp.w = hw[6] | (hw[7] << 16);
    ((uint4*)hi)[i] = hp;
}

// ============================ fast stage kernel (flattened 3-buffer pipeline) ============================
__global__ __launch_bounds__(256, 2) void rvq_stage_fast(
    const float* __restrict__ resin,
    float*       __restrict__ resout,
    const float* __restrict__ cb,      // fp32 codebook of this stage
    float*       __restrict__ codes,
    int stage, int write_hi)
{
    extern __shared__ char smem[];
    const uint32_t sb = smem_u32(smem);
    const int tid = threadIdx.x, lane = tid & 31, wid = tid >> 5;
    const int warpM = wid & 3, warpN = wid >> 2;
    const int row0 = blockIdx.x * BM;

    float* sC2 = (float*)(smem + S_C2);
    float* cV1 = (float*)(smem + S_CV1);
    int*   cI1 = (int*)  (smem + S_CI1);
    float* cV2 = (float*)(smem + S_CV2);
    float* bV1 = (float*)(smem + S_BV1);
    int*   bI1 = (int*)  (smem + S_BI1);
    float* bV2 = (float*)(smem + S_BV2);

    if (tid < BM) { bV1[tid] = 3.4e38f; bI1[tid] = 0x7fffffff; bV2[tid] = 3.4e38f; }
    // whole-stage c2 (1024 floats)
    #pragma unroll
    for (int j = 0; j < 4; j++) sC2[tid + j * 256] = g_c2[stage * V_DIM + tid + j * 256];

    const __half* gA = g_r_hi + (size_t)row0 * D_DIM;
    const __half* gB = g_cb_hi + (size_t)stage * V_DIM * D_DIM;

    // load A+B chunk c (vpass = c>>3, kchunk = c&7) into buffer c%3
    auto load_chunk = [&](int c) {
        const int vbase = (c >> 3) * BN;
        const int kb = (c & 7) * KC;
        const int buf = c % 3;
        const uint32_t abase = sb + SA + buf * 16384;
        const uint32_t bbase = sb + SB + buf * 16384;
        #pragma unroll
        for (int it = 0; it < 4; it++) {
            int u = tid + it * 256;          // 0..1023
            int row = u >> 3, seg = u & 7;   // 128 rows x 8 16B-segs
            uint32_t soff = swz((uint32_t)(row * 128 + seg * 16));
            CP_ASYNC16(abase + soff, gA + (size_t)row * D_DIM + kb + seg * 8);
            CP_ASYNC16(bbase + soff, gB + (size_t)(vbase + row) * D_DIM + kb + seg * 8);
        }
    };

    // prologue: two chunks in flight
    load_chunk(0); CP_COMMIT();
    load_chunk(1); CP_COMMIT();

    const int a_row = warpM * 32 + (lane & 15);
    const int a_kh  = (lane >> 4) * 8;
    const int b_row = warpN * 64 + ((lane >> 4) & 1) * 8 + (lane & 7);
    const int b_kh  = ((lane >> 3) & 1) * 8;

    float acc[2][8][4];
    #pragma unroll
    for (int mt = 0; mt < 2; mt++)
        #pragma unroll
        for (int na = 0; na < 8; na++)
            #pragma unroll
            for (int r = 0; r < 4; r++) acc[mt][na][r] = 0.f;

    for (int c = 0; c < NCH_ALL; c++) {
        if (c < NCH_ALL - 1) CP_WAIT1(); else CP_WAIT0();   // chunk c resident
        __syncthreads();                                      // buffer c%3 released by all warps
        if (c + 2 < NCH_ALL) { load_chunk(c + 2); CP_COMMIT(); }

        const uint32_t aH = sb + SA + (c % 3) * 16384;
        const uint32_t bH = sb + SB + (c % 3) * 16384;

        #pragma unroll
        for (int ks = 0; ks < 4; ks++) {
            uint32_t ah[2][4], bh[4][4];
            #pragma unroll
            for (int mt = 0; mt < 2; mt++) {
                uint32_t off = swz((uint32_t)((a_row + mt * 16) * 128 + (ks * 16 + a_kh) * 2));
                LDSM4(ah[mt], aH + off);
            }
            #pragma unroll
            for (int np = 0; np < 4; np++) {
                uint32_t off = swz((uint32_t)((b_row + np * 16) * 128 + (ks * 16 + b_kh) * 2));
                LDSM4(bh[np], bH + off);
            }
            #pragma unroll
            for (int mt = 0; mt < 2; mt++)
                #pragma unroll
                for (int np = 0; np < 4; np++)
                    #pragma unroll
                    for (int h = 0; h < 2; h++)
                        MMA16816(acc[mt][np * 2 + h], ah[mt], bh[np][2 * h], bh[np][2 * h + 1]);
        }

        if ((c & 7) == 7) {
            // ---- epilogue for vpass vb: scores + per-row TOP-2 ----
            const int vb = (c >> 3) * BN;
            {
                const int rbase = warpM * 32 + (lane >> 2);
                const int cgrp = (lane & 3) * 2;
                #pragma unroll
                for (int mt = 0; mt < 2; mt++) {
                    #pragma unroll
                    for (int h = 0; h < 2; h++) {
                        const int row = rbase + mt * 16 + h * 8;
                        float b1 = 3.4e38f, b2 = 3.4e38f;
                        int i1 = 0x7fffffff;
                        #pragma unroll
                        for (int na = 0; na < 8; na++) {
                            #pragma unroll
                            for (int cc = 0; cc < 2; cc++) {
                                int col = warpN * 64 + na * 8 + cgrp + cc;
                                float sc = fmaf(acc[mt][na][h * 2 + cc], -DESCALE2, sC2[vb + col]);
                                if (sc < b1) { b2 = b1; b1 = sc; i1 = vb + col; }
                                else b2 = fminf(b2, sc);
                            }
                        }
                        #pragma unroll
                        for (int o = 1; o <= 2; o <<= 1) {
                            float ob1 = __shfl_xor_sync(0xffffffffu, b1, o);
                            int   oi1 = __shfl_xor_sync(0xffffffffu, i1, o);
                            float ob2 = __shfl_xor_sync(0xffffffffu, b2, o);
                            if (ob1 < b1 || (ob1 == b1 && oi1 < i1)) {
                                b2 = fminf(b1, ob2); b1 = ob1; i1 = oi1;
                            } else {
                                b2 = fminf(b2, ob1);
                            }
                        }
                        if ((lane & 3) == 0) {
                            cV1[row * 2 + warpN] = b1;
                            cI1[row * 2 + warpN] = i1;
                            cV2[row * 2 + warpN] = b2;
                        }
                    }
                }
            }
            __syncthreads();
            if (tid < BM) {
                float a1 = bV1[tid], a2 = bV2[tid];
                int ai = bI1[tid];
                #pragma unroll
                for (int g = 0; g < 2; g++) {
                    float c1 = cV1[tid * 2 + g], c2v = cV2[tid * 2 + g];
                    int ci = cI1[tid * 2 + g];
                    if (c1 < a1 || (c1 == a1 && ci < ai)) {
                        a2 = fminf(a1, c2v); a1 = c1; ai = ci;
                    } else {
                        a2 = fminf(a2, c1);
                    }
                }
                bV1[tid] = a1; bI1[tid] = ai; bV2[tid] = a2;
            }
            __syncthreads();

            // reset accumulators for the next vpass
            #pragma unroll
            for (int mt = 0; mt < 2; mt++)
                #pragma unroll
                for (int na = 0; na < 8; na++)
                    #pragma unroll
                    for (int r = 0; r < 4; r++) acc[mt][na][r] = 0.f;
        }
    }

    // ---- write fast codes; flag small-margin rows for exact rescue ----
    if (tid < BM) {
        int row = row0 + tid;
        codes[(size_t)row * KSTAGES + stage] = (float)bI1[tid];
        if (bV2[tid] - bV1[tid] < TAU) {
            int p = atomicAdd(&g_cnt, 1);
            g_list[p] = row;
        }
    }
    __syncthreads();

    // ---- fused residual update + fp16 split for the next stage ----
    {
        const int urow_off = tid >> 7;           // 0 or 1
        const int ucol = (tid & 127) * 4;        // covers all 512 cols
        for (int r = 0; r < BM; r += 2) {
            int row = r + urow_off;
            int best = bI1[row];
            const float4 rv = *(const float4*)&resin[(size_t)(row0 + row) * D_DIM + ucol];
            const float4 qv = *(const float4*)&cb[(size_t)best * D_DIM + ucol];
            float4 o;
            o.x = __fsub_rn(rv.x, qv.x); o.y = __fsub_rn(rv.y, qv.y);
            o.z = __fsub_rn(rv.z, qv.z); o.w = __fsub_rn(rv.w, qv.w);
            *(float4*)&resout[(size_t)(row0 + row) * D_DIM + ucol] = o;
            if (write_hi) {
                uint32_t h0 = (uint32_t)__half_as_ushort(__float2half_rn(o.x)) |
                              ((uint32_t)__half_as_ushort(__float2half_rn(o.y)) << 16);
                uint32_t h1 = (uint32_t)__half_as_ushort(__float2half_rn(o.z)) |
                              ((uint32_t)__half_as_ushort(__float2half_rn(o.w)) << 16);
                uint2 hp = make_uint2(h0, h1);
                *(uint2*)&g_r_hi[(size_t)(row0 + row) * D_DIM + ucol] = hp;
            }
        }
    }
}

// ============================ exact rescue (coalesced, 16 rows/block, fused patch) ============================
__global__ __launch_bounds__(256, 2) void rvq_rescue(
    const float* __restrict__ resin,
    float*       __restrict__ resout,
    const float* __restrict__ cb,
    float* __restrict__ codes,
    int stage, int write_hi)
{
    __shared__ float rs[RROWS][D_DIM];
    __shared__ float r2s[RROWS];
    __shared__ float wbv[RROWS][8];
    __shared__ int   wbi[RROWS][8];
    __shared__ int   sfi[RROWS];
    const int tid = threadIdx.x, lane = tid & 31, wid = tid >> 5;
    const int cnt = *(volatile int*)&g_cnt;

    for (int base = blockIdx.x * RROWS; base < cnt; base += gridDim.x * RROWS) {
        const int nrows = min(RROWS, cnt - base);

        for (int r = 0; r < nrows; r++) {
            const int row = g_list[base + r];
            const float4* src = (const float4*)&resin[(size_t)row * D_DIM];
            for (int k = tid; k < D_DIM / 4; k += 256)
                ((float4*)rs[r])[k] = src[k];
        }
        __syncthreads();

        if (tid < nrows) {
            float s = 0.f, c = 0.f;
            for (int k = 0; k < D_DIM; k++)
                kahan_add(s, c, __fmul_rn(rs[tid][k], rs[tid][k]));
            r2s[tid] = __fadd_rn(s, c);
        }
        __syncthreads();

        float bv[RROWS];
        int   bi[RROWS];
        #pragma unroll
        for (int r = 0; r < RROWS; r++) { bv[r] = 3.4e38f; bi[r] = 0x7fffffff; }

        for (int v = wid; v < V_DIM; v += 8) {
            const float* cv = cb + (size_t)v * D_DIM;
            float acc[RROWS];
            #pragma unroll
            for (int r = 0; r < RROWS; r++) acc[r] = 0.f;
            #pragma unroll 2
            for (int kk = 0; kk < D_DIM; kk += 32) {
                float c = cv[kk + lane];
                #pragma unroll
                for (int r = 0; r < RROWS; r++)
                    acc[r] = fmaf(c, rs[r][kk + lane], acc[r]);
            }
            #pragma unroll
            for (int r = 0; r < RROWS; r++) {
                #pragma unroll
                for (int o = 16; o > 0; o >>= 1)
                    acc[r] += __shfl_xor_sync(0xffffffffu, acc[r], o);
            }
            const float c2v = g_c2[stage * V_DIM + v];
            #pragma unroll
            for (int r = 0; r < RROWS; r++) {
                float sc = __fadd_rn(__fsub_rn(r2s[r], __fmul_rn(2.f, acc[r])), c2v);
                if (sc < bv[r]) { bv[r] = sc; bi[r] = v; }
            }
        }
        if (lane == 0) {
            #pragma unroll
            for (int r = 0; r < RROWS; r++) { wbv[r][wid] = bv[r]; wbi[r][wid] = bi[r]; }
        }
        __syncthreads();

        if (tid < nrows) {
            float fb = 3.4e38f;
            int fi = 0x7fffffff;
            #pragma unroll
            for (int w = 0; w < 8; w++) {
                float v = wbv[tid][w];
                int i = wbi[tid][w];
                if (v < fb || (v == fb && i < fi)) { fb = v; fi = i; }
            }
            sfi[tid] = fi;
            codes[(size_t)g_list[base + tid] * KSTAGES + stage] = (float)fi;
        }
        __syncthreads();

        for (int r = 0; r < nrows; r++) {
            const int row = g_list[base + r];
            const int best = sfi[r];
            const float* cv = cb + (size_t)best * D_DIM;
            for (int k = tid * 2; k < D_DIM; k += 512) {
                float o0 = __fsub_rn(rs[r][k],     cv[k]);
                float o1 = __fsub_rn(rs[r][k + 1], cv[k + 1]);
                *(float2*)&resout[(size_t)row * D_DIM + k] = make_float2(o0, o1);
                if (write_hi) {
                    uint32_t hp = (uint32_t)__half_as_ushort(__float2half_rn(o0)) |
                                  ((uint32_t)__half_as_ushort(__float2half_rn(o1)) << 16);
                    *(uint32_t*)&g_r_hi[(size_t)row * D_DIM + k] = hp;
                }
            }
        }
        __syncthreads();
    }
}

// ---------------------------------------------------------------------------
__global__ void rvq_quant_kernel(const float4* __restrict__ x,
                                 const float4* __restrict__ res,
                                 float4* __restrict__ q, int n4) {
    int i = blockIdx.x * blockDim.x + threadIdx.x;
    if (i < n4) {
        float4 a = x[i], b = res[i];
        float4 o;
        o.x = __fsub_rn(a.x, b.x); o.y = __fsub_rn(a.y, b.y);
        o.z = __fsub_rn(a.z, b.z); o.w = __fsub_rn(a.w, b.w);
        q[i] = o;
    }
}

extern "C" void kernel_launch(void* const* d_in, const int* in_sizes, int n_in,
                              void* d_out, int out_size) {
    const float* x   = (const float*)d_in[0];       // [N, 512]
    const float* cbs = (const float*)d_in[1];       // [4, 1024, 512]
    const int N = in_sizes[0] / D_DIM;

    float* out   = (float*)d_out;
    float* codes = out;                               // [N, 4]
    float* quant = out + (size_t)N * KSTAGES;         // [N, 512] (ping buffer)
    float* res   = quant + (size_t)N * D_DIM;         // [N, 512] (pong buffer)

    cudaFuncSetAttribute(rvq_stage_fast,
                         cudaFuncAttributeMaxDynamicSharedMemorySize, SMEM_FAST);

    __half *cb_hi, *r_hi;
    int* cnt_ptr;
    cudaGetSymbolAddress((void**)&cb_hi, g_cb_hi);
    cudaGetSymbolAddress((void**)&r_hi,  g_r_hi);
    cudaGetSymbolAddress((void**)&cnt_ptr, g_cnt);

    // codebook norms + fp16 hi codebook + fp16 image of x
    rvq_c2_kernel<<<(KSTAGES * V_DIM * 32 + 255) / 256, 256>>>(cbs);
    {
        size_t n8 = (size_t)KSTAGES * V_DIM * D_DIM / 8;
        rvq_split_hi<<<(unsigned)((n8 + 255) / 256), 256>>>(cbs, cb_hi, SCALE_B, n8);
    }
    {
        size_t nr8 = (size_t)N * D_DIM / 8;
        rvq_split_hi<<<(unsigned)((nr8 + 255) / 256), 256>>>(x, r_hi, 1.0f, nr8);
    }

    // ping-pong residual: s0: x->quant, s1: quant->res, s2: res->quant, s3: quant->res
    const float* rin_seq[KSTAGES]  = { x,     quant, res,   quant };
    float*       rout_seq[KSTAGES] = { quant, res,   quant, res   };

    for (int s = 0; s < KSTAGES; s++) {
        const float* cb_s = cbs + (size_t)s * V_DIM * D_DIM;
        const int write_hi = (s < KSTAGES - 1) ? 1 : 0;
        cudaMemsetAsync(cnt_ptr, 0, sizeof(int));
        rvq_stage_fast<<<N / BM, 256, SMEM_FAST>>>(
            rin_seq[s], rout_seq[s], cb_s, codes, s, write_hi);
        rvq_rescue<<<148, 256>>>(rin_seq[s], rout_seq[s], cb_s, codes, s, write_hi);
    }

    // quantized = x - residual (final residual lives in `res`)
    int n4 = N * D_DIM / 4;
    rvq_quant_kernel<<<(n4 + 255) / 256, 256>>>(
        (const float4*)x, (const float4*)res, (float4*)quant, n4);
}

// round 14
// speedup vs baseline: 1.3107x; 1.3107x over previous
#include <cuda_runtime.h>
#include <cuda_fp16.h>
#include <cstdint>

#define D_DIM   512
#define V_DIM   1024
#define KSTAGES 4
#define N_FIX   65536

#define BM      128
#define BN      128
#define KC      64
#define NCHUNK  (D_DIM / KC)   // 8
#define NVPASS  (V_DIM / BN)   // 8

#define SCALE_B    32.0f       // exact power of 2 (codebook hi split)
#define DESCALE2   0.0625f     // 2 / SCALE_B
#define TAU        2.5e-3f     // rescue margin (~7 sigma of hi-only score error)

// ---- shared memory layout (fast kernel, bytes) ----
#define SA      0                // [2 buf][128*64 halves] = 32768
#define SB      32768            // [2 buf][128*64 halves] = 32768
#define S_C2    65536            // 1024 floats (whole stage) = 4096
#define S_CV1   69632            // 256 floats
#define S_CI1   70656            // 256 ints
#define S_CV2   71680            // 256 floats
#define S_BV1   72704            // 128 floats
#define S_BI1   73216            // 128 ints
#define S_BV2   73728            // 128 floats
#define SMEM_FAST 74240

#define RROWS   8                // rescue rows batched per block

// ---- static device scratch (no runtime allocation) ----
__device__ float  g_c2[KSTAGES * V_DIM];
__device__ __half g_cb_hi[KSTAGES * V_DIM * D_DIM];
__device__ __half g_r_hi [(size_t)N_FIX * D_DIM];
__device__ int    g_cnt;
__device__ int    g_list[N_FIX];

// ============================ asm helpers ============================
__device__ __forceinline__ uint32_t smem_u32(const void* p) {
    uint32_t a;
    asm("{ .reg .u64 t; cvta.to.shared.u64 t, %1; cvt.u32.u64 %0, t; }" : "=r"(a) : "l"(p));
    return a;
}
__device__ __forceinline__ uint32_t swz(uint32_t off) { return off ^ ((off >> 3) & 0x70); }

#define CP_ASYNC16(s, g) asm volatile("cp.async.cg.shared.global [%0], [%1], 16;" :: "r"(s), "l"(g))
#define CP_COMMIT()      asm volatile("cp.async.commit_group;" ::: "memory")
#define CP_WAIT0()       asm volatile("cp.async.wait_group 0;" ::: "memory")

#define LDSM4(d, a) \
    asm volatile("ldmatrix.sync.aligned.m8n8.x4.shared.b16 {%0,%1,%2,%3}, [%4];" \
        : "=r"((d)[0]), "=r"((d)[1]), "=r"((d)[2]), "=r"((d)[3]) : "r"(a))

#define MMA16816(c, a, b0, b1) \
    asm volatile("mma.sync.aligned.m16n8k16.row.col.f32.f16.f16.f32 " \
        "{%0,%1,%2,%3},{%4,%5,%6,%7},{%8,%9},{%0,%1,%2,%3};" \
        : "+f"((c)[0]), "+f"((c)[1]), "+f"((c)[2]), "+f"((c)[3]) \
        : "r"((a)[0]), "r"((a)[1]), "r"((a)[2]), "r"((a)[3]), "r"(b0), "r"(b1))

__device__ __forceinline__ void kahan_add(float& s, float& c, float y) {
    float t1 = __fsub_rn(y, c);
    float t2 = __fadd_rn(s, t1);
    c = __fsub_rn(__fsub_rn(t2, s), t1);
    s = t2;
}

// ============================ small kernels ============================
__global__ void rvq_c2_kernel(const float* __restrict__ cb) {
    int w = (blockIdx.x * blockDim.x + threadIdx.x) >> 5;
    int lane = threadIdx.x & 31;
    if (w >= KSTAGES * V_DIM) return;
    const float* v = cb + (size_t)w * D_DIM;
    double s = 0.0;
    for (int i = lane; i < D_DIM; i += 32) {
        float t = v[i];
        s += (double)__fmul_rn(t, t);
    }
    #pragma unroll
    for (int o = 16; o > 0; o >>= 1) s += __shfl_xor_sync(0xffffffffu, s, o);
    if (lane == 0) g_c2[w] = (float)s;
}

// hi-split: dst = fl16(scale * src); scale is an exact power of 2
__global__ void rvq_split_hi(const float* __restrict__ src, __half* __restrict__ hi,
                             float scale, size_t n8) {
    size_t i = (size_t)blockIdx.x * blockDim.x + threadIdx.x;
    if (i >= n8) return;
    const float4* p = (const float4*)(src + i * 8);
    float4 a = p[0], b = p[1];
    float v[8] = {a.x, a.y, a.z, a.w, b.x, b.y, b.z, b.w};
    uint4 hp;
    uint32_t hw[8];
    #pragma unroll
    for (int j = 0; j < 8; j++)
        hw[j] = (uint32_t)__half_as_ushort(__float2half_rn(__fmul_rn(v[j], scale)));
    hp.x = hw[0] | (hw[1] << 16);
    hp.y = hw[2] | (hw[3] << 16);
    hp.z = hw[4] | (hw[5] << 16);
    hp.w = hw[6] | (hw[7] << 16);
    ((uint4*)hi)[i] = hp;
}

// ============================ fast stage kernel (R11 champion structure) ============================
__global__ __launch_bounds__(256, 2) void rvq_stage_fast(
    const float* __restrict__ resin,
    float*       __restrict__ resout,
    const float* __restrict__ cb,      // fp32 codebook of this stage
    float*       __restrict__ codes,
    int stage, int write_hi)
{
    extern __shared__ char smem[];
    const uint32_t sb = smem_u32(smem);
    const int tid = threadIdx.x, lane = tid & 31, wid = tid >> 5;
    const int warpM = wid & 3, warpN = wid >> 2;
    const int row0 = blockIdx.x * BM;

    float* sC2 = (float*)(smem + S_C2);
    float* cV1 = (float*)(smem + S_CV1);
    int*   cI1 = (int*)  (smem + S_CI1);
    float* cV2 = (float*)(smem + S_CV2);
    float* bV1 = (float*)(smem + S_BV1);
    int*   bI1 = (int*)  (smem + S_BI1);
    float* bV2 = (float*)(smem + S_BV2);

    if (tid < BM) { bV1[tid] = 3.4e38f; bI1[tid] = 0x7fffffff; bV2[tid] = 3.4e38f; }
    #pragma unroll
    for (int j = 0; j < 4; j++) sC2[tid + j * 256] = g_c2[stage * V_DIM + tid + j * 256];

    const __half* gA = g_r_hi + (size_t)row0 * D_DIM;
    const __half* gB = g_cb_hi + (size_t)stage * V_DIM * D_DIM;

    auto load_chunk = [&](int vbase, int ci, int buf) {
        const int kb = ci * KC;
        const uint32_t abase = sb + SA + buf * 16384;
        const uint32_t bbase = sb + SB + buf * 16384;
        #pragma unroll
        for (int it = 0; it < 4; it++) {
            int u = tid + it * 256;          // 0..1023
            int row = u >> 3, seg = u & 7;   // 128 rows x 8 16B-segs
            uint32_t soff = swz((uint32_t)(row * 128 + seg * 16));
            CP_ASYNC16(abase + soff, gA + (size_t)row * D_DIM + kb + seg * 8);
            CP_ASYNC16(bbase + soff, gB + (size_t)(vbase + row) * D_DIM + kb + seg * 8);
        }
    };

    load_chunk(0, 0, 0);
    CP_COMMIT();

    const int a_row = warpM * 32 + (lane & 15);
    const int a_kh  = (lane >> 4) * 8;
    const int b_row = warpN * 64 + ((lane >> 4) & 1) * 8 + (lane & 7);
    const int b_kh  = ((lane >> 3) & 1) * 8;

    for (int vp = 0; vp < NVPASS; vp++) {
        const int vb = vp * BN;

        float acc[2][8][4];
        #pragma unroll
        for (int mt = 0; mt < 2; mt++)
            #pragma unroll
            for (int na = 0; na < 8; na++)
                #pragma unroll
                for (int r = 0; r < 4; r++) acc[mt][na][r] = 0.f;

        for (int i = 0; i < NCHUNK; i++) {
            CP_WAIT0();          // chunk i resident in buf i&1
            __syncthreads();     // all warps done with buf (i-1)&1; chunk i visible
            if (i + 1 < NCHUNK) {
                load_chunk(vb, i + 1, (i + 1) & 1);
                CP_COMMIT();
            }

            const uint32_t aH = sb + SA + (i & 1) * 16384;
            const uint32_t bH = sb + SB + (i & 1) * 16384;

            #pragma unroll
            for (int ks = 0; ks < 4; ks++) {
                uint32_t ah[2][4], bh[4][4];
                #pragma unroll
                for (int mt = 0; mt < 2; mt++) {
                    uint32_t off = swz((uint32_t)((a_row + mt * 16) * 128 + (ks * 16 + a_kh) * 2));
                    LDSM4(ah[mt], aH + off);
                }
                #pragma unroll
                for (int np = 0; np < 4; np++) {
                    uint32_t off = swz((uint32_t)((b_row + np * 16) * 128 + (ks * 16 + b_kh) * 2));
                    LDSM4(bh[np], bH + off);
                }
                #pragma unroll
                for (int mt = 0; mt < 2; mt++)
                    #pragma unroll
                    for (int np = 0; np < 4; np++)
                        #pragma unroll
                        for (int h = 0; h < 2; h++)
                            MMA16816(acc[mt][np * 2 + h], ah[mt], bh[np][2 * h], bh[np][2 * h + 1]);
            }
        }

        // prefetch next vpass chunk 0 into buf 0 (overlaps the epilogue)
        if (vp + 1 < NVPASS) {
            load_chunk(vb + BN, 0, 0);
            CP_COMMIT();
        }

        // ---- epilogue: scores + per-row TOP-2 over this 128-code pass ----
        {
            const int rbase = warpM * 32 + (lane >> 2);
            const int cgrp = (lane & 3) * 2;
            #pragma unroll
            for (int mt = 0; mt < 2; mt++) {
                #pragma unroll
                for (int h = 0; h < 2; h++) {
                    const int row = rbase + mt * 16 + h * 8;
                    float b1 = 3.4e38f, b2 = 3.4e38f;
                    int i1 = 0x7fffffff;
                    #pragma unroll
                    for (int na = 0; na < 8; na++) {
                        #pragma unroll
                        for (int c = 0; c < 2; c++) {
                            int col = warpN * 64 + na * 8 + cgrp + c;
                            float sc = fmaf(acc[mt][na][h * 2 + c], -DESCALE2, sC2[vb + col]);
                            if (sc < b1) { b2 = b1; b1 = sc; i1 = vb + col; }
                            else b2 = fminf(b2, sc);
                        }
                    }
                    #pragma unroll
                    for (int o = 1; o <= 2; o <<= 1) {
                        float ob1 = __shfl_xor_sync(0xffffffffu, b1, o);
                        int   oi1 = __shfl_xor_sync(0xffffffffu, i1, o);
                        float ob2 = __shfl_xor_sync(0xffffffffu, b2, o);
                        if (ob1 < b1 || (ob1 == b1 && oi1 < i1)) {
                            b2 = fminf(b1, ob2); b1 = ob1; i1 = oi1;
                        } else {
                            b2 = fminf(b2, ob1);
                        }
                    }
                    if ((lane & 3) == 0) {
                        cV1[row * 2 + warpN] = b1;
                        cI1[row * 2 + warpN] = i1;
                        cV2[row * 2 + warpN] = b2;
                    }
                }
            }
        }
        __syncthreads();
        if (tid < BM) {
            float a1 = bV1[tid], a2 = bV2[tid];
            int ai = bI1[tid];
            #pragma unroll
            for (int g = 0; g < 2; g++) {
                float c1 = cV1[tid * 2 + g], c2v = cV2[tid * 2 + g];
                int ci = cI1[tid * 2 + g];
                if (c1 < a1 || (c1 == a1 && ci < ai)) {
                    a2 = fminf(a1, c2v); a1 = c1; ai = ci;
                } else {
                    a2 = fminf(a2, c1);
                }
            }
            bV1[tid] = a1; bI1[tid] = ai; bV2[tid] = a2;
        }
        __syncthreads();
    }

    // ---- write fast codes; flag small-margin rows for exact rescue ----
    if (tid < BM) {
        int row = row0 + tid;
        codes[(size_t)row * KSTAGES + stage] = (float)bI1[tid];
        if (bV2[tid] - bV1[tid] < TAU) {
            int p = atomicAdd(&g_cnt, 1);
            g_list[p] = row;
        }
    }
    __syncthreads();

    // ---- fused residual update (+ fp16 split unless final stage) ----
    {
        const int urow_off = tid >> 7;           // 0 or 1
        const int ucol = (tid & 127) * 4;        // covers all 512 cols
        if (write_hi) {
            for (int r = 0; r < BM; r += 2) {
                int row = r + urow_off;
                int best = bI1[row];
                const float4 rv = *(const float4*)&resin[(size_t)(row0 + row) * D_DIM + ucol];
                const float4 qv = *(const float4*)&cb[(size_t)best * D_DIM + ucol];
                float4 o;
                o.x = __fsub_rn(rv.x, qv.x); o.y = __fsub_rn(rv.y, qv.y);
                o.z = __fsub_rn(rv.z, qv.z); o.w = __fsub_rn(rv.w, qv.w);
                *(float4*)&resout[(size_t)(row0 + row) * D_DIM + ucol] = o;
                uint32_t h0 = (uint32_t)__half_as_ushort(__float2half_rn(o.x)) |
                              ((uint32_t)__half_as_ushort(__float2half_rn(o.y)) << 16);
                uint32_t h1 = (uint32_t)__half_as_ushort(__float2half_rn(o.z)) |
                              ((uint32_t)__half_as_ushort(__float2half_rn(o.w)) << 16);
                uint2 hp = make_uint2(h0, h1);
                *(uint2*)&g_r_hi[(size_t)(row0 + row) * D_DIM + ucol] = hp;
            }
        } else {
            for (int r = 0; r < BM; r += 2) {
                int row = r + urow_off;
                int best = bI1[row];
                const float4 rv = *(const float4*)&resin[(size_t)(row0 + row) * D_DIM + ucol];
                const float4 qv = *(const float4*)&cb[(size_t)best * D_DIM + ucol];
                float4 o;
                o.x = __fsub_rn(rv.x, qv.x); o.y = __fsub_rn(rv.y, qv.y);
                o.z = __fsub_rn(rv.z, qv.z); o.w = __fsub_rn(rv.w, qv.w);
                *(float4*)&resout[(size_t)(row0 + row) * D_DIM + ucol] = o;
            }
        }
    }
}

// ============================ exact rescue (R11 form: 8 rows/block, fused patch) ============================
__global__ __launch_bounds__(256, 2) void rvq_rescue(
    const float* __restrict__ resin,
    float*       __restrict__ resout,
    const float* __restrict__ cb,
    float* __restrict__ codes,
    int stage, int write_hi)
{
    __shared__ float rs[RROWS][D_DIM];
    __shared__ float r2s[RROWS];
    __shared__ float wbv[RROWS][8];
    __shared__ int   wbi[RROWS][8];
    __shared__ int   sfi[RROWS];
    const int tid = threadIdx.x, lane = tid & 31, wid = tid >> 5;
    const int cnt = *(volatile int*)&g_cnt;

    for (int base = blockIdx.x * RROWS; base < cnt; base += gridDim.x * RROWS) {
        const int nrows = min(RROWS, cnt - base);

        for (int r = 0; r < nrows; r++) {
            const int row = g_list[base + r];
            const float4* src = (const float4*)&resin[(size_t)row * D_DIM];
            for (int k = tid; k < D_DIM / 4; k += 256)
                ((float4*)rs[r])[k] = src[k];
        }
        __syncthreads();

        if (tid < nrows) {
            float s = 0.f, c = 0.f;
            for (int k = 0; k < D_DIM; k++)
                kahan_add(s, c, __fmul_rn(rs[tid][k], rs[tid][k]));
            r2s[tid] = __fadd_rn(s, c);
        }
        __syncthreads();

        float bv[RROWS];
        int   bi[RROWS];
        #pragma unroll
        for (int r = 0; r < RROWS; r++) { bv[r] = 3.4e38f; bi[r] = 0x7fffffff; }

        for (int v = wid; v < V_DIM; v += 8) {
            const float* cv = cb + (size_t)v * D_DIM;
            float acc[RROWS];
            #pragma unroll
            for (int r = 0; r < RROWS; r++) acc[r] = 0.f;
            #pragma unroll 4
            for (int kk = 0; kk < D_DIM; kk += 32) {
                float c = cv[kk + lane];
                #pragma unroll
                for (int r = 0; r < RROWS; r++)
                    acc[r] = fmaf(c, rs[r][kk + lane], acc[r]);
            }
            #pragma unroll
            for (int r = 0; r < RROWS; r++) {
                #pragma unroll
                for (int o = 16; o > 0; o >>= 1)
                    acc[r] += __shfl_xor_sync(0xffffffffu, acc[r], o);
            }
            const float c2v = g_c2[stage * V_DIM + v];
            #pragma unroll
            for (int r = 0; r < RROWS; r++) {
                float sc = __fadd_rn(__fsub_rn(r2s[r], __fmul_rn(2.f, acc[r])), c2v);
                if (sc < bv[r]) { bv[r] = sc; bi[r] = v; }
            }
        }
        if (lane == 0) {
            #pragma unroll
            for (int r = 0; r < RROWS; r++) { wbv[r][wid] = bv[r]; wbi[r][wid] = bi[r]; }
        }
        __syncthreads();

        if (tid < nrows) {
            float fb = 3.4e38f;
            int fi = 0x7fffffff;
            #pragma unroll
            for (int w = 0; w < 8; w++) {
                float v = wbv[tid][w];
                int i = wbi[tid][w];
                if (v < fb || (v == fb && i < fi)) { fb = v; fi = i; }
            }
            sfi[tid] = fi;
            codes[(size_t)g_list[base + tid] * KSTAGES + stage] = (float)fi;
        }
        __syncthreads();

        for (int r = 0; r < nrows; r++) {
            const int row = g_list[base + r];
            const int best = sfi[r];
            const float* cv = cb + (size_t)best * D_DIM;
            for (int k = tid * 2; k < D_DIM; k += 512) {
                float o0 = __fsub_rn(rs[r][k],     cv[k]);
                float o1 = __fsub_rn(rs[r][k + 1], cv[k + 1]);
                *(float2*)&resout[(size_t)row * D_DIM + k] = make_float2(o0, o1);
                if (write_hi) {
                    uint32_t hp = (uint32_t)__half_as_ushort(__float2half_rn(o0)) |
                                  ((uint32_t)__half_as_ushort(__float2half_rn(o1)) << 16);
                    *(uint32_t*)&g_r_hi[(size_t)row * D_DIM + k] = hp;
                }
            }
        }
        __syncthreads();
    }
}

// ---------------------------------------------------------------------------
__global__ void rvq_quant_kernel(const float4* __restrict__ x,
                                 const float4* __restrict__ res,
                                 float4* __restrict__ q, int n4) {
    int i = blockIdx.x * blockDim.x + threadIdx.x;
    if (i < n4) {
        float4 a = x[i], b = res[i];
        float4 o;
        o.x = __fsub_rn(a.x, b.x); o.y = __fsub_rn(a.y, b.y);
        o.z = __fsub_rn(a.z, b.z); o.w = __fsub_rn(a.w, b.w);
        q[i] = o;
    }
}

extern "C" void kernel_launch(void* const* d_in, const int* in_sizes, int n_in,
                              void* d_out, int out_size) {
    const float* x   = (const float*)d_in[0];       // [N, 512]
    const float* cbs = (const float*)d_in[1];       // [4, 1024, 512]
    const int N = in_sizes[0] / D_DIM;

    float* out   = (float*)d_out;
    float* codes = out;                               // [N, 4]
    float* quant = out + (size_t)N * KSTAGES;         // [N, 512] (ping buffer)
    float* res   = quant + (size_t)N * D_DIM;         // [N, 512] (pong buffer)

    cudaFuncSetAttribute(rvq_stage_fast,
                         cudaFuncAttributeMaxDynamicSharedMemorySize, SMEM_FAST);

    __half *cb_hi, *r_hi;
    int* cnt_ptr;
    cudaGetSymbolAddress((void**)&cb_hi, g_cb_hi);
    cudaGetSymbolAddress((void**)&r_hi,  g_r_hi);
    cudaGetSymbolAddress((void**)&cnt_ptr, g_cnt);

    // codebook norms + fp16 hi codebook + fp16 image of x
    rvq_c2_kernel<<<(KSTAGES * V_DIM * 32 + 255) / 256, 256>>>(cbs);
    {
        size_t n8 = (size_t)KSTAGES * V_DIM * D_DIM / 8;
        rvq_split_hi<<<(unsigned)((n8 + 255) / 256), 256>>>(cbs, cb_hi, SCALE_B, n8);
    }
    {
        size_t nr8 = (size_t)N * D_DIM / 8;
        rvq_split_hi<<<(unsigned)((nr8 + 255) / 256), 256>>>(x, r_hi, 1.0f, nr8);
    }

    // ping-pong residual: s0: x->quant, s1: quant->res, s2: res->quant, s3: quant->res
    const float* rin_seq[KSTAGES]  = { x,     quant, res,   quant };
    float*       rout_seq[KSTAGES] = { quant, res,   quant, res   };

    for (int s = 0; s < KSTAGES; s++) {
        const float* cb_s = cbs + (size_t)s * V_DIM * D_DIM;
        const int write_hi = (s < KSTAGES - 1) ? 1 : 0;
        cudaMemsetAsync(cnt_ptr, 0, sizeof(int));
        rvq_stage_fast<<<N / BM, 256, SMEM_FAST>>>(
            rin_seq[s], rout_seq[s], cb_s, codes, s, write_hi);
        rvq_rescue<<<296, 256>>>(rin_seq[s], rout_seq[s], cb_s, codes, s, write_hi);
    }

    // quantized = x - residual (final residual lives in `res`)
    int n4 = N * D_DIM / 4;
    rvq_quant_kernel<<<(n4 + 255) / 256, 256>>>(
        (const float4*)x, (const float4*)res, (float4*)quant, n4);
}